// round 4
// baseline (speedup 1.0000x reference)
#include <cuda_runtime.h>
#include <cuda_fp16.h>

#define N_NODES 50000
#define N_EDGES 1600000
#define BATCH   4
#define T_STEPS 50
#define DT      0.02f
#define EDGE_MAX (N_EDGES + 4 * N_NODES)
#define TN (T_STEPS * N_NODES)
#define NB 132          // co-residency margin: 132 blocks on >=148 SMs
#define NT 1024

// ---- scratch (static device globals; no allocation allowed) ----
__device__ int      g_deg[N_NODES];
__device__ int      g_row_start[N_NODES + 1];
__device__ int      g_cursor[N_NODES];
__device__ unsigned g_edges[EDGE_MAX];          // (src<<16) | fp16(weight)
__device__ float4   g_rates[2][N_NODES];        // double-buffered relu(v), batch-vec
__device__ float    g_alpha[N_NODES];
__device__ unsigned g_bar_count;

// ---------------------------------------------------------------------------
// Setup kernels
// ---------------------------------------------------------------------------

__global__ void init_kernel(const float* __restrict__ bias,
                            const float* __restrict__ tc) {
    int i = blockIdx.x * blockDim.x + threadIdx.x;
    if (i >= N_NODES) return;
    if (i == 0) g_bar_count = 0u;               // reset per graph replay
    g_deg[i] = 0;
    float b   = bias[i];
    float tau = fmaxf(tc[i], DT);
    g_alpha[i] = DT / tau;
    float r = fmaxf(b, 0.0f);
    g_rates[0][i] = make_float4(r, r, r, r);
}

__global__ void hist_kernel(const int* __restrict__ tgt) {
    int e = blockIdx.x * blockDim.x + threadIdx.x;
    if (e < N_EDGES) atomicAdd(&g_deg[tgt[e]], 1);
}

// single-block tiled exclusive scan over degrees padded to multiples of 4
__global__ void scan_kernel() {
    __shared__ int warp_sums[32];
    __shared__ int s_carry;
    int lane = threadIdx.x & 31;
    int wid  = threadIdx.x >> 5;
    if (threadIdx.x == 0) s_carry = 0;
    __syncthreads();
    for (int base = 0; base < N_NODES; base += 1024) {
        int i   = base + threadIdx.x;
        int val = (i < N_NODES) ? ((g_deg[i] + 3) & ~3) : 0;
        int inc = val;
        #pragma unroll
        for (int d = 1; d < 32; d <<= 1) {
            int y = __shfl_up_sync(0xffffffffu, inc, d);
            if (lane >= d) inc += y;
        }
        if (lane == 31) warp_sums[wid] = inc;
        __syncthreads();
        if (wid == 0) {
            int w = warp_sums[lane];
            #pragma unroll
            for (int d = 1; d < 32; d <<= 1) {
                int y = __shfl_up_sync(0xffffffffu, w, d);
                if (lane >= d) w += y;
            }
            warp_sums[lane] = w;
        }
        __syncthreads();
        int excl = s_carry + (inc - val) + (wid > 0 ? warp_sums[wid - 1] : 0);
        if (i < N_NODES) { g_row_start[i] = excl; g_cursor[i] = excl; }
        int tile_total = warp_sums[31];
        __syncthreads();
        if (threadIdx.x == 0) s_carry += tile_total;
        __syncthreads();
    }
    if (threadIdx.x == 0) g_row_start[N_NODES] = s_carry;
}

__global__ void build_kernel(const int*   __restrict__ src,
                             const int*   __restrict__ tgt,
                             const float* __restrict__ sign,
                             const float* __restrict__ cnt,
                             const float* __restrict__ strg) {
    int e = blockIdx.x * blockDim.x + threadIdx.x;
    if (e >= N_EDGES) return;
    float w = sign[e] * fmaxf(cnt[e], 0.0f) * fmaxf(strg[e], 0.0f);
    unsigned hw = (unsigned)__half_as_ushort(__float2half_rn(w));
    unsigned packed = ((unsigned)src[e] << 16) | hw;
    int pos = atomicAdd(&g_cursor[tgt[e]], 1);
    g_edges[pos] = packed;
}

// zero only the <=3 padding entries per node (src=0, w=+0.0h dummies)
__global__ void pad_kernel() {
    int n = blockIdx.x * blockDim.x + threadIdx.x;
    if (n >= N_NODES) return;
    int e   = g_cursor[n];
    int end = g_row_start[n + 1];
    for (; e < end; e++) g_edges[e] = 0u;
}

// ---------------------------------------------------------------------------
// Persistent simulation kernel: all 50 steps in one launch.
// 4 lanes (a quad) per node; each lane takes every 4th 4-edge chunk
// (LDG.128 of packed edges + 4 L2 gathers), quad shfl reduce, lane q owns
// batch q's Euler state IN REGISTERS for the whole simulation.
// Software grid barrier between steps (132 co-resident blocks).
// ---------------------------------------------------------------------------

__device__ __forceinline__ float gather_quad(const uint4* __restrict__ ep,
                                             int nch, int q,
                                             const float4* __restrict__ rr) {
    float ax = 0.f, ay = 0.f, az = 0.f, aw = 0.f;
    for (int c = q; c < nch; c += 4) {
        uint4 e4 = __ldg(&ep[c]);
        int s0 = e4.x >> 16, s1 = e4.y >> 16, s2 = e4.z >> 16, s3 = e4.w >> 16;
        float w0 = __half2float(__ushort_as_half((unsigned short)(e4.x & 0xFFFFu)));
        float w1 = __half2float(__ushort_as_half((unsigned short)(e4.y & 0xFFFFu)));
        float w2 = __half2float(__ushort_as_half((unsigned short)(e4.z & 0xFFFFu)));
        float w3 = __half2float(__ushort_as_half((unsigned short)(e4.w & 0xFFFFu)));
        float4 r0 = __ldcg(&rr[s0]);   // .cg: L2 only — coherent across barrier
        float4 r1 = __ldcg(&rr[s1]);
        float4 r2 = __ldcg(&rr[s2]);
        float4 r3 = __ldcg(&rr[s3]);
        ax += r0.x * w0 + r1.x * w1 + r2.x * w2 + r3.x * w3;
        ay += r0.y * w0 + r1.y * w1 + r2.y * w2 + r3.y * w3;
        az += r0.z * w0 + r1.z * w1 + r2.z * w2 + r3.z * w3;
        aw += r0.w * w0 + r1.w * w1 + r2.w * w2 + r3.w * w3;
    }
    // quad reduction (post-loop, warp fully reconverged)
    #pragma unroll
    for (int off = 1; off <= 2; off <<= 1) {
        ax += __shfl_xor_sync(0xffffffffu, ax, off);
        ay += __shfl_xor_sync(0xffffffffu, ay, off);
        az += __shfl_xor_sync(0xffffffffu, az, off);
        aw += __shfl_xor_sync(0xffffffffu, aw, off);
    }
    return (q == 0) ? ax : (q == 1) ? ay : (q == 2) ? az : aw;
}

__global__ __launch_bounds__(NT, 1)
void sim_kernel(const float* __restrict__ x,
                const float* __restrict__ bias,
                float* __restrict__ out) {
    const int blk = blockIdx.x;
    const int tid = threadIdx.x;
    const int node_beg = (int)(((long long)N_NODES * blk) / NB);
    const int node_end = (int)(((long long)N_NODES * (blk + 1)) / NB);
    const int slot_beg = node_beg << 2;
    const int slot_end = node_end << 2;

    // Slot A always valid (>=1512 slots per block, 1024 threads, <=2048 total).
    int sA = slot_beg + tid;
    int sB = sA + NT;
    bool validB = sB < slot_end;
    bool warpB  = __any_sync(0xffffffffu, validB);   // warp-uniform round-B flag

    int nA = sA >> 2, qA = sA & 3;
    int begA = g_row_start[nA];
    int nchA = (g_row_start[nA + 1] - begA) >> 2;
    const uint4* epA = (const uint4*)&g_edges[begA];
    float bA = bias[nA];
    float aA = g_alpha[nA];
    float vA = bA;
    int  xiA = qA * TN + nA;

    int nB = 0, qB = 0, nchB = 0, xiB = 0;
    const uint4* epB = (const uint4*)g_edges;
    float bB = 0.f, aB = 0.f, vB = 0.f;
    if (validB) {
        nB = sB >> 2; qB = sB & 3;
        int begB = g_row_start[nB];
        nchB = (g_row_start[nB + 1] - begB) >> 2;
        epB = (const uint4*)&g_edges[begB];
        bB = bias[nB]; aB = g_alpha[nB]; vB = bB;
        xiB = qB * TN + nB;
    }

    int parity = 0;
    for (int t = 0; t < T_STEPS; t++) {
        const float4* rr = g_rates[parity];
        float* wr = (float*)g_rates[parity ^ 1];

        float sumA = gather_quad(epA, nchA, qA, rr);
        vA += aA * (bA - vA + sumA + __ldcs(&x[xiA]));
        float rA = fmaxf(vA, 0.f);
        wr[(nA << 2) + qA] = rA;
        __stcs(&out[xiA], rA);
        xiA += N_NODES;

        if (warpB) {
            float sumB = gather_quad(epB, nchB, qB, rr);
            if (validB) {
                vB += aB * (bB - vB + sumB + __ldcs(&x[xiB]));
                float rB = fmaxf(vB, 0.f);
                wr[(nB << 2) + qB] = rB;
                __stcs(&out[xiB], rB);
                xiB += N_NODES;
            }
        }

        // ---- software grid barrier (release: every thread fences) ----
        __threadfence();                           // publish this thread's stores
        __syncthreads();
        if (tid == 0) {
            atomicAdd(&g_bar_count, 1u);
            unsigned target = (unsigned)NB * (unsigned)(t + 1);
            while (*(volatile unsigned*)&g_bar_count < target) {
                __nanosleep(64);                   // throttled poll
            }
        }
        __syncthreads();
        parity ^= 1;
    }
}

// ---------------------------------------------------------------------------

extern "C" void kernel_launch(void* const* d_in, const int* in_sizes, int n_in,
                              void* d_out, int out_size) {
    const float* x    = (const float*)d_in[0];
    const float* bias = (const float*)d_in[1];
    const float* tc   = (const float*)d_in[2];
    const float* sign = (const float*)d_in[3];
    const float* cnt  = (const float*)d_in[4];
    const float* strg = (const float*)d_in[5];
    const int*   src  = (const int*)d_in[6];
    const int*   tgt  = (const int*)d_in[7];
    float*       out  = (float*)d_out;

    int nb = (N_NODES + 255) / 256;
    int eb = (N_EDGES + 255) / 256;

    init_kernel<<<nb, 256>>>(bias, tc);
    hist_kernel<<<eb, 256>>>(tgt);
    scan_kernel<<<1, 1024>>>();
    build_kernel<<<eb, 256>>>(src, tgt, sign, cnt, strg);
    pad_kernel<<<nb, 256>>>();
    sim_kernel<<<NB, NT>>>(x, bias, out);
}

// round 5
// speedup vs baseline: 1.3755x; 1.3755x over previous
#include <cuda_runtime.h>
#include <cuda_fp16.h>

#define N_NODES 50000
#define N_EDGES 1600000
#define BATCH   4
#define T_STEPS 50
#define DT      0.02f
#define EDGE_MAX (N_EDGES + 4 * N_NODES)
#define TN (T_STEPS * N_NODES)

// ---- scratch (static device globals; no allocation allowed) ----
__device__ int      g_deg[N_NODES];
__device__ int      g_row_start[N_NODES + 1];
__device__ int      g_cursor[N_NODES];
__device__ unsigned g_edges[EDGE_MAX];          // (src<<16) | fp16(weight)
__device__ float4   g_rates[2][N_NODES];        // double-buffered relu(v), batch-vec
__device__ float    g_alpha[N_NODES];
__device__ float    g_v[BATCH][N_NODES];        // planar membrane state

// ---------------------------------------------------------------------------
// Setup kernels
// ---------------------------------------------------------------------------

__global__ void init_kernel(const float* __restrict__ bias,
                            const float* __restrict__ tc) {
    int i = blockIdx.x * blockDim.x + threadIdx.x;
    if (i >= N_NODES) return;
    g_deg[i] = 0;
    float b   = bias[i];
    float tau = fmaxf(tc[i], DT);
    g_alpha[i] = DT / tau;
    float r = fmaxf(b, 0.0f);
    #pragma unroll
    for (int q = 0; q < BATCH; q++) g_v[q][i] = b;
    g_rates[0][i] = make_float4(r, r, r, r);
}

__global__ void hist_kernel(const int* __restrict__ tgt) {
    int e = blockIdx.x * blockDim.x + threadIdx.x;
    if (e < N_EDGES) atomicAdd(&g_deg[tgt[e]], 1);
}

// single-block tiled exclusive scan over degrees padded to multiples of 4
__global__ void scan_kernel() {
    __shared__ int warp_sums[32];
    __shared__ int s_carry;
    int lane = threadIdx.x & 31;
    int wid  = threadIdx.x >> 5;
    if (threadIdx.x == 0) s_carry = 0;
    __syncthreads();
    for (int base = 0; base < N_NODES; base += 1024) {
        int i   = base + threadIdx.x;
        int val = (i < N_NODES) ? ((g_deg[i] + 3) & ~3) : 0;
        int inc = val;
        #pragma unroll
        for (int d = 1; d < 32; d <<= 1) {
            int y = __shfl_up_sync(0xffffffffu, inc, d);
            if (lane >= d) inc += y;
        }
        if (lane == 31) warp_sums[wid] = inc;
        __syncthreads();
        if (wid == 0) {
            int w = warp_sums[lane];
            #pragma unroll
            for (int d = 1; d < 32; d <<= 1) {
                int y = __shfl_up_sync(0xffffffffu, w, d);
                if (lane >= d) w += y;
            }
            warp_sums[lane] = w;
        }
        __syncthreads();
        int excl = s_carry + (inc - val) + (wid > 0 ? warp_sums[wid - 1] : 0);
        if (i < N_NODES) { g_row_start[i] = excl; g_cursor[i] = excl; }
        int tile_total = warp_sums[31];
        __syncthreads();
        if (threadIdx.x == 0) s_carry += tile_total;
        __syncthreads();
    }
    if (threadIdx.x == 0) g_row_start[N_NODES] = s_carry;
}

__global__ void build_kernel(const int*   __restrict__ src,
                             const int*   __restrict__ tgt,
                             const float* __restrict__ sign,
                             const float* __restrict__ cnt,
                             const float* __restrict__ strg) {
    int e = blockIdx.x * blockDim.x + threadIdx.x;
    if (e >= N_EDGES) return;
    float w = sign[e] * fmaxf(cnt[e], 0.0f) * fmaxf(strg[e], 0.0f);
    unsigned hw = (unsigned)__half_as_ushort(__float2half_rn(w));
    unsigned packed = ((unsigned)src[e] << 16) | hw;
    int pos = atomicAdd(&g_cursor[tgt[e]], 1);
    g_edges[pos] = packed;
}

// zero only the <=3 padding entries per node (src=0, w=+0.0h dummies)
__global__ void pad_kernel() {
    int n = blockIdx.x * blockDim.x + threadIdx.x;
    if (n >= N_NODES) return;
    int e   = g_cursor[n];
    int end = g_row_start[n + 1];
    for (; e < end; e++) g_edges[e] = 0u;
}

// ---------------------------------------------------------------------------
// Step kernel: 4 lanes (one quad) per target node; lane q takes every 4th
// 4-edge chunk. Packed f32x2 accumulation (2 FFMA2/edge), 2-chunk pipelined
// gathers (8 loads in flight), quad shfl_xor reduce, lane q owns batch q's
// Euler update. L1-cached gathers are coherent because L1 flushes per launch.
// ---------------------------------------------------------------------------

// one edge word -> accumulate into (a01, a23) f32x2 carriers
__device__ __forceinline__ void edge_acc(unsigned word,
                                         const ulonglong2* __restrict__ rd,
                                         unsigned long long& a01,
                                         unsigned long long& a23) {
    int s = word >> 16;
    float w = __half2float(__ushort_as_half((unsigned short)word));
    unsigned long long wp;
    asm("mov.b64 %0, {%1, %1};" : "=l"(wp) : "f"(w));
    ulonglong2 r = __ldg(&rd[s]);     // 16B: (r.x,r.y) | (r.z,r.w) bit carriers
    asm("fma.rn.f32x2 %0, %1, %2, %0;" : "+l"(a01) : "l"(r.x), "l"(wp));
    asm("fma.rn.f32x2 %0, %1, %2, %0;" : "+l"(a23) : "l"(r.y), "l"(wp));
}

__global__ __launch_bounds__(256)
void step_kernel(const float* __restrict__ x,
                 const float* __restrict__ bias,
                 float* __restrict__ out,
                 int t, int parity) {
    int gtid = blockIdx.x * blockDim.x + threadIdx.x;
    int n    = gtid >> 2;
    if (n >= N_NODES) return;
    int q = threadIdx.x & 3;

    const ulonglong2* __restrict__ rd = (const ulonglong2*)g_rates[parity];
    int beg = g_row_start[n];
    int nch = (g_row_start[n + 1] - beg) >> 2;
    const uint4* ep = (const uint4*)&g_edges[beg];

    // prefetch stimulus early (streaming)
    int   o  = t * N_NODES + n;
    int   xi = q * TN + o;
    float xv = __ldcs(&x[xi]);

    unsigned long long a01 = 0ull, a23 = 0ull;
    int c = q;
    // pipeline 2 chunks: 2 edge-word LDG.128 + 8 rate gathers in flight
    for (; c + 4 < nch; c += 8) {
        uint4 eA = __ldg(&ep[c]);
        uint4 eB = __ldg(&ep[c + 4]);
        edge_acc(eA.x, rd, a01, a23);
        edge_acc(eA.y, rd, a01, a23);
        edge_acc(eA.z, rd, a01, a23);
        edge_acc(eA.w, rd, a01, a23);
        edge_acc(eB.x, rd, a01, a23);
        edge_acc(eB.y, rd, a01, a23);
        edge_acc(eB.z, rd, a01, a23);
        edge_acc(eB.w, rd, a01, a23);
    }
    if (c < nch) {
        uint4 eA = __ldg(&ep[c]);
        edge_acc(eA.x, rd, a01, a23);
        edge_acc(eA.y, rd, a01, a23);
        edge_acc(eA.z, rd, a01, a23);
        edge_acc(eA.w, rd, a01, a23);
    }

    // quad reduction in packed form (warp fully reconverged here)
    #pragma unroll
    for (int off = 1; off <= 2; off <<= 1) {
        unsigned long long o01 = __shfl_xor_sync(0xffffffffu, a01, off);
        unsigned long long o23 = __shfl_xor_sync(0xffffffffu, a23, off);
        asm("add.rn.f32x2 %0, %0, %1;" : "+l"(a01) : "l"(o01));
        asm("add.rn.f32x2 %0, %0, %1;" : "+l"(a23) : "l"(o23));
    }
    float s0, s1, s2, s3;
    asm("mov.b64 {%0, %1}, %2;" : "=f"(s0), "=f"(s1) : "l"(a01));
    asm("mov.b64 {%0, %1}, %2;" : "=f"(s2), "=f"(s3) : "l"(a23));
    float sum = (q == 0) ? s0 : (q == 1) ? s1 : (q == 2) ? s2 : s3;

    float b = bias[n];
    float a = g_alpha[n];
    float v = g_v[q][n];
    v += a * (b - v + sum + xv);
    g_v[q][n] = v;

    float r = fmaxf(v, 0.f);
    ((float*)g_rates[parity ^ 1])[(n << 2) + q] = r;
    __stcs(&out[xi], r);
}

// ---------------------------------------------------------------------------

extern "C" void kernel_launch(void* const* d_in, const int* in_sizes, int n_in,
                              void* d_out, int out_size) {
    const float* x    = (const float*)d_in[0];
    const float* bias = (const float*)d_in[1];
    const float* tc   = (const float*)d_in[2];
    const float* sign = (const float*)d_in[3];
    const float* cnt  = (const float*)d_in[4];
    const float* strg = (const float*)d_in[5];
    const int*   src  = (const int*)d_in[6];
    const int*   tgt  = (const int*)d_in[7];
    float*       out  = (float*)d_out;

    int nb = (N_NODES + 255) / 256;
    int eb = (N_EDGES + 255) / 256;
    int sb = (N_NODES * 4 + 255) / 256;

    init_kernel<<<nb, 256>>>(bias, tc);
    hist_kernel<<<eb, 256>>>(tgt);
    scan_kernel<<<1, 1024>>>();
    build_kernel<<<eb, 256>>>(src, tgt, sign, cnt, strg);
    pad_kernel<<<nb, 256>>>();

    for (int t = 0; t < T_STEPS; t++)
        step_kernel<<<sb, 256>>>(x, bias, out, t, t & 1);
}